// round 2
// baseline (speedup 1.0000x reference)
#include <cuda_runtime.h>
#include <cstdint>

#define NN 20
#define CH 512
#define HH 64
#define WW 64
#define PIX 4096
#define CHW (CH*PIX)
#define CL 300
#define CV 512
#define CIN_M (CV+CL)
#define WT (9*CH*CH)

#define T_RST 0
#define T_UPD 1
#define T_OUT 2

// ---------------- device scratch (static; no allocations) ----------------
__device__ float g_vis[CHW];           // vis_part = mconv_vis ⊛ vis + mconv_b
__device__ float g_A[3][CHW];          // conv(vis_part, Wtype_half1) + bias_type
__device__ float g_beta[NN][CH];       // per-node lang channel vector
__device__ float g_tv[3][NN][9][CH];   // per-tap matvecs of beta
__device__ float g_cls[3][NN][9][CH];  // 9 border-class sums of tv
__device__ float g_Wt1[3][WT];         // W[:, :512] transposed -> [tap][ci][co]
__device__ float g_Wt2[3][WT];         // W[:, 512:] transposed -> [tap][ci][co]
__device__ float g_h[NN][CHW];
__device__ float g_cs[NN][CHW];        // ch_sum per node (accumulated)
__device__ float g_rh[NN][CHW];        // reset_hidden per node (accumulated)
__device__ float g_z[CHW];
__device__ float g_o[CHW];
__device__ int   g_parent[NN];
__device__ int   g_ccount[NN];

// ---------------- tree structure ----------------
__global__ void k_tree(const int* __restrict__ adj) {
    int t = threadIdx.x;
    if (t < NN) {
        int cnt = 0;
        for (int c = 0; c < NN; c++) cnt += (adj[t*NN + c] != 0);
        g_ccount[t] = cnt;
        int par = -1;
        for (int p = 0; p < NN; p++) if (adj[p*NN + t] != 0) par = p;
        g_parent[t] = par;
    }
}

// ---------------- beta[n][co] = W_lang[co,:] . lang[n,:] ----------------
__global__ void k_beta(const float* __restrict__ mw, const float* __restrict__ lang) {
    int n = blockIdx.x;
    int co = threadIdx.x;
    __shared__ float sl[CL];
    for (int i = threadIdx.x; i < CL; i += blockDim.x) sl[i] = lang[n*CL + i];
    __syncthreads();
    const float* wrow = mw + (size_t)co*CIN_M + CV;
    float acc = 0.f;
    for (int k = 0; k < CL; k++) acc += wrow[k] * sl[k];
    g_beta[n][co] = acc;
}

// ---------------- transpose conv weights [co][ci][tap] -> [tap][ci][co] halves ----------------
__global__ void k_transw(const float* __restrict__ wr, const float* __restrict__ wu,
                         const float* __restrict__ wo) {
    const float* w = (blockIdx.z == 0) ? wr : ((blockIdx.z == 1) ? wu : wo);
    __shared__ float tile[32][33];
    int X0 = blockIdx.x * 32;   // over ci*9+tap (0..9215)
    int co0 = blockIdx.y * 32;  // over cout (0..511)
    int tx = threadIdx.x, ty = threadIdx.y;
    tile[ty][tx] = w[(size_t)(co0 + ty) * (1024*9) + X0 + tx];
    __syncthreads();
    int X = X0 + ty;
    int ci = X / 9, tap = X % 9;
    float v = tile[tx][ty];
    float* dst = (ci < CH) ? g_Wt1[blockIdx.z] : g_Wt2[blockIdx.z];
    int cil = ci & (CH - 1);
    dst[((size_t)tap*CH + cil)*CH + co0 + tx] = v;
}

// ---------------- vis_part GEMM: [512co x 4096p] = mw_vis[512x512] @ vis[512x4096] + b ----------------
__global__ void __launch_bounds__(256) k_visgemm(const float* __restrict__ mw,
                                                 const float* __restrict__ mb,
                                                 const float* __restrict__ vis) {
    __shared__ float As[16][64];
    __shared__ float Bs[16][64];
    int p0 = blockIdx.x * 64, co0 = blockIdx.y * 64;
    int tid = threadIdx.x;
    int cg = tid / 16, pg = tid % 16;
    float acc[4][4];
#pragma unroll
    for (int i = 0; i < 4; i++)
#pragma unroll
        for (int j = 0; j < 4; j++) acc[i][j] = 0.f;

    for (int k0 = 0; k0 < CV; k0 += 16) {
        __syncthreads();
        for (int l = tid; l < 64*16; l += 256) {
            int k = l % 16, co = l / 16;
            As[k][co] = mw[(size_t)(co0 + co)*CIN_M + k0 + k];
        }
        for (int l = tid; l < 16*64; l += 256) {
            int p = l % 64, k = l / 64;
            Bs[k][p] = vis[(size_t)(k0 + k)*PIX + p0 + p];
        }
        __syncthreads();
#pragma unroll
        for (int k = 0; k < 16; k++) {
            float4 a = *(const float4*)&As[k][cg*4];
            float4 b = *(const float4*)&Bs[k][pg*4];
            float av[4] = {a.x, a.y, a.z, a.w};
            float bv[4] = {b.x, b.y, b.z, b.w};
#pragma unroll
            for (int i = 0; i < 4; i++)
#pragma unroll
                for (int j = 0; j < 4; j++) acc[i][j] += av[i]*bv[j];
        }
    }
    for (int i = 0; i < 4; i++)
        for (int j = 0; j < 4; j++) {
            int co = co0 + cg*4 + i, p = p0 + pg*4 + j;
            g_vis[(size_t)co*PIX + p] = acc[i][j] + mb[co];
        }
}

// ---------------- tap matvecs: tv[type][n][tap][co] = sum_ci Wt1[tap][ci][co]*beta[n][ci] ----------------
__global__ void k_tapv() {
    int b = blockIdx.x;
    int type = b / (NN*9);
    int r = b % (NN*9);
    int n = r / 9, tap = r % 9;
    __shared__ float sb[CH];
    sb[threadIdx.x] = g_beta[n][threadIdx.x];
    __syncthreads();
    int co = threadIdx.x;
    const float* w = g_Wt1[type] + (size_t)tap*CH*CH + co;
    float acc = 0.f;
    for (int ci = 0; ci < CH; ci++) acc += w[(size_t)ci*CH] * sb[ci];
    g_tv[type][n][tap][co] = acc;
}

// ---------------- border-class sums ----------------
__global__ void k_cls() {
    int type = blockIdx.x / NN, n = blockIdx.x % NN;
    int co = threadIdx.x;
    float tv[9];
#pragma unroll
    for (int t = 0; t < 9; t++) tv[t] = g_tv[type][n][t][co];
#pragma unroll
    for (int yc = 0; yc < 3; yc++)
#pragma unroll
        for (int xc = 0; xc < 3; xc++) {
            float s = 0.f;
#pragma unroll
            for (int dy = 0; dy < 3; dy++) {
                if (yc == 0 && dy == 0) continue;
                if (yc == 2 && dy == 2) continue;
#pragma unroll
                for (int dx = 0; dx < 3; dx++) {
                    if (xc == 0 && dx == 0) continue;
                    if (xc == 2 && dx == 2) continue;
                    s += tv[dy*3 + dx];
                }
            }
            g_cls[type][n][yc*3 + xc][co] = s;
        }
}

// ---------------- core 3x3-conv implicit-GEMM tile (shared by all conv kernels) ----------------
// Computes acc[8][8] for output tile: couts [co0, co0+128), rows {r0, r0+1}, cols 0..63.
// Thread mapping: cg = tid&15 -> 8 couts, pg = tid>>4 -> (rr = pg>>3 row, seg8 = (pg&7)*8 col seg).
__device__ __forceinline__ void conv_gemm(
    const float* __restrict__ in, const float* __restrict__ Wt,
    float As[8][9][128], float Bs[8][4][68], float acc[8][8],
    int r0, int co0, int tid, int rr, int seg8, int cg)
{
    for (int k0 = 0; k0 < CH; k0 += 8) {
        __syncthreads();
        // load weights chunk: As[ci][tap][co] (2304 float4s, 9 per thread)
#pragma unroll
        for (int i = 0; i < 9; i++) {
            int l = tid + i*256;
            int co4 = l & 31;
            int tmp = l >> 5;
            int tap = tmp % 9, ci = tmp / 9;
            const float4* src = (const float4*)(Wt + ((size_t)(tap*CH + k0 + ci))*CH + co0) + co4;
            *(((float4*)&As[ci][tap][0]) + co4) = *src;
        }
        // load input halo tile: rows r0-1..r0+2, cols -1..64 (+pad)
        for (int l = tid; l < 8*4*68; l += 256) {
            int bcol = l % 68;
            int r = (l / 68) & 3;
            int ci = l / 272;
            int ir = r0 - 1 + r, ic = bcol - 1;
            float v = 0.f;
            if (ir >= 0 && ir < HH && ic >= 0 && ic < WW)
                v = in[(size_t)(k0 + ci)*PIX + ir*WW + ic];
            Bs[ci][r][bcol] = v;
        }
        __syncthreads();
#pragma unroll 1
        for (int ci = 0; ci < 8; ci++) {
#pragma unroll
            for (int dy = 0; dy < 3; dy++) {
                float4 w0 = *(const float4*)&Bs[ci][rr + dy][seg8];
                float4 w1 = *(const float4*)&Bs[ci][rr + dy][seg8 + 4];
                float4 w2 = *(const float4*)&Bs[ci][rr + dy][seg8 + 8];
                float bw[12] = {w0.x, w0.y, w0.z, w0.w,
                                w1.x, w1.y, w1.z, w1.w,
                                w2.x, w2.y, w2.z, w2.w};
#pragma unroll
                for (int dx = 0; dx < 3; dx++) {
                    float4 a0 = *(const float4*)&As[ci][dy*3 + dx][cg*8];
                    float4 a1 = *(const float4*)&As[ci][dy*3 + dx][cg*8 + 4];
                    float av[8] = {a0.x, a0.y, a0.z, a0.w, a1.x, a1.y, a1.z, a1.w};
#pragma unroll
                    for (int i = 0; i < 8; i++)
#pragma unroll
                        for (int j = 0; j < 8; j++)
                            acc[i][j] += av[i] * bw[j + dx];
                }
            }
        }
    }
}

// ---------------- MODE 0: precompute A_type = conv(vis_part, W1) + bias ----------------
__global__ void __launch_bounds__(256) k_conv_pre(
    const float* __restrict__ in, const float* __restrict__ Wt,
    const float* __restrict__ bias, float* __restrict__ out)
{
    __shared__ float As[8][9][128];
    __shared__ float Bs[8][4][68];
    int r0 = blockIdx.x * 2, co0 = blockIdx.y * 128;
    int tid = threadIdx.x;
    int pg = tid >> 4, cg = tid & 15;
    int rr = pg >> 3, seg8 = (pg & 7) * 8;

    float acc[8][8];
#pragma unroll
    for (int i = 0; i < 8; i++)
#pragma unroll
        for (int j = 0; j < 8; j++) acc[i][j] = 0.f;

    conv_gemm(in, Wt, As, Bs, acc, r0, co0, tid, rr, seg8, cg);

    int row = r0 + rr;
#pragma unroll
    for (int i = 0; i < 8; i++) {
        int co = co0 + cg*8 + i;
#pragma unroll
        for (int j = 0; j < 8; j++) {
            int col = seg8 + j;
            out[(size_t)co*PIX + row*WW + col] = acc[i][j] + bias[co];
        }
    }
}

// ---------------- fused z & o for node c (blockIdx.z: 0 -> z/update, 1 -> o/output) ----------------
// z = sigmoid(A_u + cls_u[c] + conv(cs[c], Wu2));  o = tanh(A_o + cls_o[c] + conv(rh[c], Wo2))
__global__ void __launch_bounds__(256) k_conv_zo(
    const float* __restrict__ in_u,  const float* __restrict__ in_o,
    const float* __restrict__ Wu,    const float* __restrict__ Wo,
    const float* __restrict__ base_u,const float* __restrict__ base_o,
    const float* __restrict__ cls_u, const float* __restrict__ cls_o,
    const int* __restrict__ skip,
    float* __restrict__ out_z, float* __restrict__ out_o)
{
    __shared__ float As[8][9][128];
    __shared__ float Bs[8][4][68];
    int which = blockIdx.z;
    const float* in   = which ? in_o   : in_u;
    const float* Wt   = which ? Wo     : Wu;
    const float* base = which ? base_o : base_u;
    const float* cls  = which ? cls_o  : cls_u;
    float* out        = which ? out_o  : out_z;

    int r0 = blockIdx.x * 2, co0 = blockIdx.y * 128;
    int tid = threadIdx.x;
    int pg = tid >> 4, cg = tid & 15;
    int rr = pg >> 3, seg8 = (pg & 7) * 8;

    float acc[8][8];
#pragma unroll
    for (int i = 0; i < 8; i++)
#pragma unroll
        for (int j = 0; j < 8; j++) acc[i][j] = 0.f;

    if (skip[0] != 0)   // leaf: cs/rh are all zero, conv contributes nothing
        conv_gemm(in, Wt, As, Bs, acc, r0, co0, tid, rr, seg8, cg);

    int row = r0 + rr;
    int yc = (row == 0) ? 0 : ((row == HH - 1) ? 2 : 1);
#pragma unroll
    for (int i = 0; i < 8; i++) {
        int co = co0 + cg*8 + i;
#pragma unroll
        for (int j = 0; j < 8; j++) {
            int col = seg8 + j;
            int xc = (col == 0) ? 0 : ((col == WW - 1) ? 2 : 1);
            size_t idx = (size_t)co*PIX + row*WW + col;
            float v = acc[i][j] + base[idx] + cls[(yc*3 + xc)*CH + co];
            out[idx] = which ? tanhf(v) : (1.f / (1.f + __expf(-v)));
        }
    }
}

// ---------------- reset conv for edge (parent(c) <- c) ----------------
// r = sigmoid(A_r + cls_r[parent] + conv(h[c], Wr2)); rh[parent] += r*h[c]; cs[parent] += h[c]
__global__ void __launch_bounds__(256) k_conv_rst(
    const float* __restrict__ in,   // h[c]
    const float* __restrict__ Wt,   // Wr2
    const float* __restrict__ base, // A_r
    const float* __restrict__ clsAll, // g_cls[T_RST] base: [NN][9][CH]
    int child,
    float* __restrict__ rhAll, float* __restrict__ csAll)
{
    __shared__ float As[8][9][128];
    __shared__ float Bs[8][4][68];
    int r0 = blockIdx.x * 2, co0 = blockIdx.y * 128;
    int tid = threadIdx.x;
    int pg = tid >> 4, cg = tid & 15;
    int rr = pg >> 3, seg8 = (pg & 7) * 8;

    float acc[8][8];
#pragma unroll
    for (int i = 0; i < 8; i++)
#pragma unroll
        for (int j = 0; j < 8; j++) acc[i][j] = 0.f;

    conv_gemm(in, Wt, As, Bs, acc, r0, co0, tid, rr, seg8, cg);

    int par = g_parent[child];
    const float* clsv = clsAll + (size_t)par * 9 * CH;
    float* rh = rhAll + (size_t)par * CHW;
    float* cs = csAll + (size_t)par * CHW;

    int row = r0 + rr;
    int yc = (row == 0) ? 0 : ((row == HH - 1) ? 2 : 1);
#pragma unroll
    for (int i = 0; i < 8; i++) {
        int co = co0 + cg*8 + i;
#pragma unroll
        for (int j = 0; j < 8; j++) {
            int col = seg8 + j;
            int xc = (col == 0) ? 0 : ((col == WW - 1) ? 2 : 1);
            size_t idx = (size_t)co*PIX + row*WW + col;
            float v = acc[i][j] + base[idx] + clsv[(yc*3 + xc)*CH + co];
            float r = 1.f / (1.f + __expf(-v));
            float hv = in[idx];
            rh[idx] += r * hv;
            cs[idx] += hv;
        }
    }
}

// ---------------- h = (1-z)*o + z*ch_sum ----------------
__global__ void k_h(const float* __restrict__ cs, float* __restrict__ h) {
    int i = blockIdx.x * blockDim.x + threadIdx.x;
    float z = g_z[i], o = g_o[i];
    h[i] = (1.f - z)*o + z*cs[i];
}

// ---------------- host orchestration (graph-capturable) ----------------
extern "C" void kernel_launch(void* const* d_in, const int* in_sizes, int n_in,
                              void* d_out, int out_size) {
    const float* vis  = (const float*)d_in[0];
    const float* lang = (const float*)d_in[1];
    const int*   adj  = (const int*)  d_in[2];
    const float* mw   = (const float*)d_in[3];
    const float* mb   = (const float*)d_in[4];
    const float* wr   = (const float*)d_in[5];
    const float* br   = (const float*)d_in[6];
    const float* wu   = (const float*)d_in[7];
    const float* bu   = (const float*)d_in[8];
    const float* wo   = (const float*)d_in[9];
    const float* bo   = (const float*)d_in[10];

    float *p_vis, *p_A, *p_cls, *p_Wt1, *p_Wt2, *p_h, *p_cs, *p_rh, *p_z, *p_o;
    int *p_cc;
    cudaGetSymbolAddress((void**)&p_vis, g_vis);
    cudaGetSymbolAddress((void**)&p_A,   g_A);
    cudaGetSymbolAddress((void**)&p_cls, g_cls);
    cudaGetSymbolAddress((void**)&p_Wt1, g_Wt1);
    cudaGetSymbolAddress((void**)&p_Wt2, g_Wt2);
    cudaGetSymbolAddress((void**)&p_h,   g_h);
    cudaGetSymbolAddress((void**)&p_cs,  g_cs);
    cudaGetSymbolAddress((void**)&p_rh,  g_rh);
    cudaGetSymbolAddress((void**)&p_z,   g_z);
    cudaGetSymbolAddress((void**)&p_o,   g_o);
    cudaGetSymbolAddress((void**)&p_cc,  g_ccount);

    k_tree<<<1, 32>>>(adj);
    k_beta<<<NN, CH>>>(mw, lang);
    {
        dim3 tg(9216/32, CH/32, 3);
        k_transw<<<tg, dim3(32, 32)>>>(wr, wu, wo);
    }
    k_visgemm<<<dim3(PIX/64, CH/64), 256>>>(mw, mb, vis);

    dim3 cgrid(32, 4);
    dim3 zgrid(32, 4, 2);
    const float* bias3[3] = {br, bu, bo};
    for (int t = 0; t < 3; t++) {
        k_conv_pre<<<cgrid, 256>>>(p_vis, p_Wt1 + (size_t)t*WT, bias3[t],
                                   p_A + (size_t)t*CHW);
    }
    k_tapv<<<3*NN*9, CH>>>();
    k_cls<<<3*NN, CH>>>();

    cudaMemsetAsync(p_cs, 0, sizeof(float)*(size_t)NN*CHW);
    cudaMemsetAsync(p_rh, 0, sizeof(float)*(size_t)NN*CHW);

    for (int c = NN - 1; c >= 0; c--) {
        // fused: z = sigmoid(A_u + cls_u[c] + conv(cs[c], Wu2))
        //        o = tanh  (A_o + cls_o[c] + conv(rh[c], Wo2))
        k_conv_zo<<<zgrid, 256>>>(
            p_cs + (size_t)c*CHW, p_rh + (size_t)c*CHW,
            p_Wt2 + (size_t)T_UPD*WT, p_Wt2 + (size_t)T_OUT*WT,
            p_A + (size_t)T_UPD*CHW,  p_A + (size_t)T_OUT*CHW,
            p_cls + ((size_t)T_UPD*NN + c)*9*CH,
            p_cls + ((size_t)T_OUT*NN + c)*9*CH,
            p_cc + c, p_z, p_o);
        // h[c] = (1-z)*o + z*ch_sum[c]
        k_h<<<CHW/256, 256>>>(p_cs + (size_t)c*CHW, p_h + (size_t)c*CHW);
        // reset toward parent: rh[p] += sigmoid(A_r + cls_r[p] + conv(h[c], Wr2))*h[c]; cs[p] += h[c]
        if (c > 0) {
            k_conv_rst<<<cgrid, 256>>>(p_h + (size_t)c*CHW,
                                       p_Wt2 + (size_t)T_RST*WT,
                                       p_A + (size_t)T_RST*CHW,
                                       p_cls + (size_t)T_RST*NN*9*CH,
                                       c, p_rh, p_cs);
        }
    }

    cudaMemcpyAsync(d_out, p_h, sizeof(float)*(size_t)CHW, cudaMemcpyDeviceToDevice);
}

// round 4
// speedup vs baseline: 1.0222x; 1.0222x over previous
#include <cuda_runtime.h>
#include <cstdint>

#define NN 20
#define CH 512
#define HH 64
#define WW 64
#define PIX 4096
#define CHW (CH*PIX)
#define CL 300
#define CV 512
#define CIN_M (CV+CL)
#define WT (9*CH*CH)

#define T_RST 0
#define T_UPD 1
#define T_OUT 2

typedef unsigned long long u64;

__device__ __forceinline__ u64 pack2(float lo, float hi) {
    u64 r; asm("mov.b64 %0, {%1, %2};" : "=l"(r) : "f"(lo), "f"(hi)); return r;
}
__device__ __forceinline__ void unpack2(u64 v, float& lo, float& hi) {
    asm("mov.b64 {%0, %1}, %2;" : "=f"(lo), "=f"(hi) : "l"(v));
}
__device__ __forceinline__ void ffma2(u64& d, u64 a, u64 b) {
    asm("fma.rn.f32x2 %0, %1, %2, %0;" : "+l"(d) : "l"(a), "l"(b));
}

// ---------------- device scratch (static; no allocations) ----------------
__device__ float g_vis[CHW];           // vis_part = mconv_vis ⊛ vis + mconv_b
__device__ float g_A[3][CHW];          // conv(vis_part, Wtype_half1) + bias_type
__device__ float g_beta[NN][CH];       // per-node lang channel vector
__device__ float g_tv[3][NN][9][CH];   // per-tap matvecs of beta
__device__ float g_cls[3][NN][9][CH];  // 9 border-class sums of tv
__device__ float g_Wt1[3][WT];         // W[:, :512] transposed -> [tap][ci][co]
__device__ float g_Wt2[3][WT];         // W[:, 512:] transposed -> [tap][ci][co]
__device__ float g_h[NN][CHW];
__device__ float g_cs[NN][CHW];        // ch_sum per node (accumulated)
__device__ float g_rh[NN][CHW];        // reset_hidden per node (accumulated)
__device__ float g_z[CHW];
__device__ float g_o[CHW];
__device__ int   g_parent[NN];
__device__ int   g_ccount[NN];

// ---------------- tree structure ----------------
__global__ void k_tree(const int* __restrict__ adj) {
    int t = threadIdx.x;
    if (t < NN) {
        int cnt = 0;
        for (int c = 0; c < NN; c++) cnt += (adj[t*NN + c] != 0);
        g_ccount[t] = cnt;
        int par = -1;
        for (int p = 0; p < NN; p++) if (adj[p*NN + t] != 0) par = p;
        g_parent[t] = par;
    }
}

// ---------------- beta[n][co] = W_lang[co,:] . lang[n,:] ----------------
__global__ void k_beta(const float* __restrict__ mw, const float* __restrict__ lang) {
    int n = blockIdx.x;
    int co = threadIdx.x;
    __shared__ float sl[CL];
    for (int i = threadIdx.x; i < CL; i += blockDim.x) sl[i] = lang[n*CL + i];
    __syncthreads();
    const float* wrow = mw + (size_t)co*CIN_M + CV;
    float acc = 0.f;
    for (int k = 0; k < CL; k++) acc += wrow[k] * sl[k];
    g_beta[n][co] = acc;
}

// ---------------- transpose conv weights [co][ci][tap] -> [tap][ci][co] halves ----------------
__global__ void k_transw(const float* __restrict__ wr, const float* __restrict__ wu,
                         const float* __restrict__ wo) {
    const float* w = (blockIdx.z == 0) ? wr : ((blockIdx.z == 1) ? wu : wo);
    __shared__ float tile[32][33];
    int X0 = blockIdx.x * 32;   // over ci*9+tap (0..9215)
    int co0 = blockIdx.y * 32;  // over cout (0..511)
    int tx = threadIdx.x, ty = threadIdx.y;
    tile[ty][tx] = w[(size_t)(co0 + ty) * (1024*9) + X0 + tx];
    __syncthreads();
    int X = X0 + ty;
    int ci = X / 9, tap = X % 9;
    float v = tile[tx][ty];
    float* dst = (ci < CH) ? g_Wt1[blockIdx.z] : g_Wt2[blockIdx.z];
    int cil = ci & (CH - 1);
    dst[((size_t)tap*CH + cil)*CH + co0 + tx] = v;
}

// ---------------- vis_part GEMM: [512co x 4096p] = mw_vis[512x512] @ vis[512x4096] + b ----------------
__global__ void __launch_bounds__(256) k_visgemm(const float* __restrict__ mw,
                                                 const float* __restrict__ mb,
                                                 const float* __restrict__ vis) {
    __shared__ float As[16][64];
    __shared__ float Bs[16][64];
    int p0 = blockIdx.x * 64, co0 = blockIdx.y * 64;
    int tid = threadIdx.x;
    int cg = tid / 16, pg = tid % 16;
    float acc[4][4];
#pragma unroll
    for (int i = 0; i < 4; i++)
#pragma unroll
        for (int j = 0; j < 4; j++) acc[i][j] = 0.f;

    for (int k0 = 0; k0 < CV; k0 += 16) {
        __syncthreads();
        for (int l = tid; l < 64*16; l += 256) {
            int k = l % 16, co = l / 16;
            As[k][co] = mw[(size_t)(co0 + co)*CIN_M + k0 + k];
        }
        for (int l = tid; l < 16*64; l += 256) {
            int p = l % 64, k = l / 64;
            Bs[k][p] = vis[(size_t)(k0 + k)*PIX + p0 + p];
        }
        __syncthreads();
#pragma unroll
        for (int k = 0; k < 16; k++) {
            float4 a = *(const float4*)&As[k][cg*4];
            float4 b = *(const float4*)&Bs[k][pg*4];
            float av[4] = {a.x, a.y, a.z, a.w};
            float bv[4] = {b.x, b.y, b.z, b.w};
#pragma unroll
            for (int i = 0; i < 4; i++)
#pragma unroll
                for (int j = 0; j < 4; j++) acc[i][j] += av[i]*bv[j];
        }
    }
    for (int i = 0; i < 4; i++)
        for (int j = 0; j < 4; j++) {
            int co = co0 + cg*4 + i, p = p0 + pg*4 + j;
            g_vis[(size_t)co*PIX + p] = acc[i][j] + mb[co];
        }
}

// ---------------- tap matvecs: tv[type][n][tap][co] = sum_ci Wt1[tap][ci][co]*beta[n][ci] ----------------
__global__ void k_tapv() {
    int b = blockIdx.x;
    int type = b / (NN*9);
    int r = b % (NN*9);
    int n = r / 9, tap = r % 9;
    __shared__ float sb[CH];
    sb[threadIdx.x] = g_beta[n][threadIdx.x];
    __syncthreads();
    int co = threadIdx.x;
    const float* w = g_Wt1[type] + (size_t)tap*CH*CH + co;
    float acc = 0.f;
    for (int ci = 0; ci < CH; ci++) acc += w[(size_t)ci*CH] * sb[ci];
    g_tv[type][n][tap][co] = acc;
}

// ---------------- border-class sums ----------------
__global__ void k_cls() {
    int type = blockIdx.x / NN, n = blockIdx.x % NN;
    int co = threadIdx.x;
    float tv[9];
#pragma unroll
    for (int t = 0; t < 9; t++) tv[t] = g_tv[type][n][t][co];
#pragma unroll
    for (int yc = 0; yc < 3; yc++)
#pragma unroll
        for (int xc = 0; xc < 3; xc++) {
            float s = 0.f;
#pragma unroll
            for (int dy = 0; dy < 3; dy++) {
                if (yc == 0 && dy == 0) continue;
                if (yc == 2 && dy == 2) continue;
#pragma unroll
                for (int dx = 0; dx < 3; dx++) {
                    if (xc == 0 && dx == 0) continue;
                    if (xc == 2 && dx == 2) continue;
                    s += tv[dy*3 + dx];
                }
            }
            g_cls[type][n][yc*3 + xc][co] = s;
        }
}

// ---------------- core 3x3-conv implicit-GEMM tile (FFMA2 / f32x2 packed) ----------------
// Output tile: couts [co0, co0+128), rows {r0, r0+1}, cols 0..63.
// Thread mapping: cg = tid&15 -> 8 couts (4 pairs), pg = tid>>4 -> (rr row, seg8 col seg).
// As2[ci][tap][p*16+cg] holds cout pair (co0+cg*8+2p, +1) as f32x2 — bank-conflict-free LDS.64.
__device__ __forceinline__ void conv_gemm(
    const float* __restrict__ in, const float* __restrict__ Wt,
    u64 (*As2)[9][64], float (*Bs)[4][68], float acc[8][8],
    int r0, int co0, int tid, int rr, int seg8, int cg)
{
    u64 acc2[4][8];
#pragma unroll
    for (int p = 0; p < 4; p++)
#pragma unroll
        for (int j = 0; j < 8; j++) acc2[p][j] = 0ull;

    for (int k0 = 0; k0 < CH; k0 += 8) {
        __syncthreads();
        // weights chunk -> paired smem layout (2304 float4 loads, 9 per thread)
#pragma unroll
        for (int i = 0; i < 9; i++) {
            int l = tid + i*256;
            int co4 = l & 31;
            int tmp = l >> 5;
            int tap = tmp % 9, ci = tmp / 9;
            float4 v = *((const float4*)(Wt + ((size_t)(tap*CH + k0 + ci))*CH + co0) + co4);
            int q0 = co4 * 2;
            As2[ci][tap][(q0 & 3)*16 + (q0 >> 2)] = pack2(v.x, v.y);
            int q1 = q0 + 1;
            As2[ci][tap][(q1 & 3)*16 + (q1 >> 2)] = pack2(v.z, v.w);
        }
        // load input halo tile: rows r0-1..r0+2, cols -1..64 (+pad)
        for (int l = tid; l < 8*4*68; l += 256) {
            int bcol = l % 68;
            int r = (l / 68) & 3;
            int ci = l / 272;
            int ir = r0 - 1 + r, ic = bcol - 1;
            float v = 0.f;
            if (ir >= 0 && ir < HH && ic >= 0 && ic < WW)
                v = in[(size_t)(k0 + ci)*PIX + ir*WW + ic];
            Bs[ci][r][bcol] = v;
        }
        __syncthreads();
#pragma unroll 1
        for (int ci = 0; ci < 8; ci++) {
#pragma unroll
            for (int dy = 0; dy < 3; dy++) {
                float4 w0 = *(const float4*)&Bs[ci][rr + dy][seg8];
                float4 w1 = *(const float4*)&Bs[ci][rr + dy][seg8 + 4];
                float4 w2 = *(const float4*)&Bs[ci][rr + dy][seg8 + 8];
                float bw[12] = {w0.x, w0.y, w0.z, w0.w,
                                w1.x, w1.y, w1.z, w1.w,
                                w2.x, w2.y, w2.z, w2.w};
                u64 bdup[10];
#pragma unroll
                for (int t = 0; t < 10; t++) bdup[t] = pack2(bw[t], bw[t]);
#pragma unroll
                for (int dx = 0; dx < 3; dx++) {
                    const u64* ap = &As2[ci][dy*3 + dx][cg];
                    u64 a0 = ap[0], a1 = ap[16], a2 = ap[32], a3 = ap[48];
#pragma unroll
                    for (int j = 0; j < 8; j++) {
                        ffma2(acc2[0][j], a0, bdup[j + dx]);
                        ffma2(acc2[1][j], a1, bdup[j + dx]);
                        ffma2(acc2[2][j], a2, bdup[j + dx]);
                        ffma2(acc2[3][j], a3, bdup[j + dx]);
                    }
                }
            }
        }
    }
#pragma unroll
    for (int p = 0; p < 4; p++)
#pragma unroll
        for (int j = 0; j < 8; j++)
            unpack2(acc2[p][j], acc[2*p][j], acc[2*p + 1][j]);
}

// ---------------- precompute A_type = conv(vis_part, W1) + bias ----------------
__global__ void __launch_bounds__(256, 2) k_conv_pre(
    const float* __restrict__ in, const float* __restrict__ Wt,
    const float* __restrict__ bias, float* __restrict__ out)
{
    __shared__ u64 As2[8][9][64];
    __shared__ float Bs[8][4][68];
    int r0 = blockIdx.x * 2, co0 = blockIdx.y * 128;
    int tid = threadIdx.x;
    int pg = tid >> 4, cg = tid & 15;
    int rr = pg >> 3, seg8 = (pg & 7) * 8;

    float acc[8][8];
    conv_gemm(in, Wt, As2, Bs, acc, r0, co0, tid, rr, seg8, cg);

    int row = r0 + rr;
#pragma unroll
    for (int i = 0; i < 8; i++) {
        int co = co0 + cg*8 + i;
#pragma unroll
        for (int j = 0; j < 8; j++) {
            int col = seg8 + j;
            out[(size_t)co*PIX + row*WW + col] = acc[i][j] + bias[co];
        }
    }
}

// ---------------- fused z & o for node c (blockIdx.z: 0 -> z/update, 1 -> o/output) ----------------
// z = sigmoid(A_u + cls_u[c] + conv(cs[c], Wu2));  o = tanh(A_o + cls_o[c] + conv(rh[c], Wo2))
__global__ void __launch_bounds__(256, 2) k_conv_zo(
    const float* __restrict__ in_u,  const float* __restrict__ in_o,
    const float* __restrict__ Wu,    const float* __restrict__ Wo,
    const float* __restrict__ base_u,const float* __restrict__ base_o,
    const float* __restrict__ cls_u, const float* __restrict__ cls_o,
    const int* __restrict__ skip,
    float* __restrict__ out_z, float* __restrict__ out_o)
{
    __shared__ u64 As2[8][9][64];
    __shared__ float Bs[8][4][68];
    int which = blockIdx.z;
    const float* in   = which ? in_o   : in_u;
    const float* Wt   = which ? Wo     : Wu;
    const float* base = which ? base_o : base_u;
    const float* cls  = which ? cls_o  : cls_u;
    float* out        = which ? out_o  : out_z;

    int r0 = blockIdx.x * 2, co0 = blockIdx.y * 128;
    int tid = threadIdx.x;
    int pg = tid >> 4, cg = tid & 15;
    int rr = pg >> 3, seg8 = (pg & 7) * 8;

    float acc[8][8];
#pragma unroll
    for (int i = 0; i < 8; i++)
#pragma unroll
        for (int j = 0; j < 8; j++) acc[i][j] = 0.f;

    if (skip[0] != 0)   // leaf: cs/rh are all zero, conv contributes nothing
        conv_gemm(in, Wt, As2, Bs, acc, r0, co0, tid, rr, seg8, cg);

    int row = r0 + rr;
    int yc = (row == 0) ? 0 : ((row == HH - 1) ? 2 : 1);
#pragma unroll
    for (int i = 0; i < 8; i++) {
        int co = co0 + cg*8 + i;
#pragma unroll
        for (int j = 0; j < 8; j++) {
            int col = seg8 + j;
            int xc = (col == 0) ? 0 : ((col == WW - 1) ? 2 : 1);
            size_t idx = (size_t)co*PIX + row*WW + col;
            float v = acc[i][j] + base[idx] + cls[(yc*3 + xc)*CH + co];
            out[idx] = which ? tanhf(v) : (1.f / (1.f + __expf(-v)));
        }
    }
}

// ---------------- reset conv for edge (parent(c) <- c) ----------------
// r = sigmoid(A_r + cls_r[parent] + conv(h[c], Wr2)); rh[parent] += r*h[c]; cs[parent] += h[c]
__global__ void __launch_bounds__(256, 2) k_conv_rst(
    const float* __restrict__ in,   // h[c]
    const float* __restrict__ Wt,   // Wr2
    const float* __restrict__ base, // A_r
    const float* __restrict__ clsAll, // g_cls[T_RST] base: [NN][9][CH]
    int child,
    float* __restrict__ rhAll, float* __restrict__ csAll)
{
    __shared__ u64 As2[8][9][64];
    __shared__ float Bs[8][4][68];
    int r0 = blockIdx.x * 2, co0 = blockIdx.y * 128;
    int tid = threadIdx.x;
    int pg = tid >> 4, cg = tid & 15;
    int rr = pg >> 3, seg8 = (pg & 7) * 8;

    float acc[8][8];
    conv_gemm(in, Wt, As2, Bs, acc, r0, co0, tid, rr, seg8, cg);

    int par = g_parent[child];
    const float* clsv = clsAll + (size_t)par * 9 * CH;
    float* rh = rhAll + (size_t)par * CHW;
    float* cs = csAll + (size_t)par * CHW;

    int row = r0 + rr;
    int yc = (row == 0) ? 0 : ((row == HH - 1) ? 2 : 1);
#pragma unroll
    for (int i = 0; i < 8; i++) {
        int co = co0 + cg*8 + i;
#pragma unroll
        for (int j = 0; j < 8; j++) {
            int col = seg8 + j;
            int xc = (col == 0) ? 0 : ((col == WW - 1) ? 2 : 1);
            size_t idx = (size_t)co*PIX + row*WW + col;
            float v = acc[i][j] + base[idx] + clsv[(yc*3 + xc)*CH + co];
            float r = 1.f / (1.f + __expf(-v));
            float hv = in[idx];
            rh[idx] += r * hv;
            cs[idx] += hv;
        }
    }
}

// ---------------- h = (1-z)*o + z*ch_sum ----------------
__global__ void k_h(const float* __restrict__ cs, float* __restrict__ h) {
    int i = blockIdx.x * blockDim.x + threadIdx.x;
    float z = g_z[i], o = g_o[i];
    h[i] = (1.f - z)*o + z*cs[i];
}

// ---------------- host orchestration (graph-capturable) ----------------
extern "C" void kernel_launch(void* const* d_in, const int* in_sizes, int n_in,
                              void* d_out, int out_size) {
    const float* vis  = (const float*)d_in[0];
    const float* lang = (const float*)d_in[1];
    const int*   adj  = (const int*)  d_in[2];
    const float* mw   = (const float*)d_in[3];
    const float* mb   = (const float*)d_in[4];
    const float* wr   = (const float*)d_in[5];
    const float* br   = (const float*)d_in[6];
    const float* wu   = (const float*)d_in[7];
    const float* bu   = (const float*)d_in[8];
    const float* wo   = (const float*)d_in[9];
    const float* bo   = (const float*)d_in[10];

    float *p_vis, *p_A, *p_cls, *p_Wt1, *p_Wt2, *p_h, *p_cs, *p_rh, *p_z, *p_o;
    int *p_cc;
    cudaGetSymbolAddress((void**)&p_vis, g_vis);
    cudaGetSymbolAddress((void**)&p_A,   g_A);
    cudaGetSymbolAddress((void**)&p_cls, g_cls);
    cudaGetSymbolAddress((void**)&p_Wt1, g_Wt1);
    cudaGetSymbolAddress((void**)&p_Wt2, g_Wt2);
    cudaGetSymbolAddress((void**)&p_h,   g_h);
    cudaGetSymbolAddress((void**)&p_cs,  g_cs);
    cudaGetSymbolAddress((void**)&p_rh,  g_rh);
    cudaGetSymbolAddress((void**)&p_z,   g_z);
    cudaGetSymbolAddress((void**)&p_o,   g_o);
    cudaGetSymbolAddress((void**)&p_cc,  g_ccount);

    k_tree<<<1, 32>>>(adj);
    k_beta<<<NN, CH>>>(mw, lang);
    {
        dim3 tg(9216/32, CH/32, 3);
        k_transw<<<tg, dim3(32, 32)>>>(wr, wu, wo);
    }
    k_visgemm<<<dim3(PIX/64, CH/64), 256>>>(mw, mb, vis);

    dim3 cgrid(32, 4);
    dim3 zgrid(32, 4, 2);
    const float* bias3[3] = {br, bu, bo};
    for (int t = 0; t < 3; t++) {
        k_conv_pre<<<cgrid, 256>>>(p_vis, p_Wt1 + (size_t)t*WT, bias3[t],
                                   p_A + (size_t)t*CHW);
    }
    k_tapv<<<3*NN*9, CH>>>();
    k_cls<<<3*NN, CH>>>();

    cudaMemsetAsync(p_cs, 0, sizeof(float)*(size_t)NN*CHW);
    cudaMemsetAsync(p_rh, 0, sizeof(float)*(size_t)NN*CHW);

    for (int c = NN - 1; c >= 0; c--) {
        // fused: z = sigmoid(A_u + cls_u[c] + conv(cs[c], Wu2))
        //        o = tanh  (A_o + cls_o[c] + conv(rh[c], Wo2))
        k_conv_zo<<<zgrid, 256>>>(
            p_cs + (size_t)c*CHW, p_rh + (size_t)c*CHW,
            p_Wt2 + (size_t)T_UPD*WT, p_Wt2 + (size_t)T_OUT*WT,
            p_A + (size_t)T_UPD*CHW,  p_A + (size_t)T_OUT*CHW,
            p_cls + ((size_t)T_UPD*NN + c)*9*CH,
            p_cls + ((size_t)T_OUT*NN + c)*9*CH,
            p_cc + c, p_z, p_o);
        // h[c] = (1-z)*o + z*ch_sum[c]
        k_h<<<CHW/256, 256>>>(p_cs + (size_t)c*CHW, p_h + (size_t)c*CHW);
        // reset toward parent: rh[p] += sigmoid(A_r + cls_r[p] + conv(h[c], Wr2))*h[c]; cs[p] += h[c]
        if (c > 0) {
            k_conv_rst<<<cgrid, 256>>>(p_h + (size_t)c*CHW,
                                       p_Wt2 + (size_t)T_RST*WT,
                                       p_A + (size_t)T_RST*CHW,
                                       p_cls + (size_t)T_RST*NN*9*CH,
                                       c, p_rh, p_cs);
        }
    }

    cudaMemcpyAsync(d_out, p_h, sizeof(float)*(size_t)CHW, cudaMemcpyDeviceToDevice);
}

// round 9
// speedup vs baseline: 2.2077x; 2.1597x over previous
#include <cuda_runtime.h>
#include <cuda_bf16.h>
#include <cstdint>

#define NN 20
#define CH 512
#define HH 64
#define WW 64
#define PIX 4096
#define CHW (CH*PIX)
#define CL 300
#define CV 512
#define CIN_M (CV+CL)
#define WT (9*CH*CH)
#define QDIM 66
#define QPIX (QDIM*QDIM)
#define NCHUNK 72            // 9 taps * 8 ci-chunks of 64
#define STAGEB 65536         // 4 tiles * 16KB
#define DSMEM (2*STAGEB + 128)

#define T_RST 0
#define T_UPD 1
#define T_OUT 2

// ---------------- device scratch ----------------
__device__ float g_vis[CHW];
__device__ float g_A[3][CHW];
__device__ float g_beta[NN][CH];
__device__ float g_tv[3][NN][9][CH];
__device__ float g_cls[3][NN][9][CH];
__device__ float g_Wt1[3][WT];                          // fp32 [tap][ci][co] for beta matvecs
__device__ __nv_bfloat16 g_Wb[(size_t)2*3*2*9*512*512]; // [hsel][type][split][tap][co][ci]
__device__ __nv_bfloat16 g_XsP[(size_t)2*QPIX*CH];      // vis_part  (hi, lo)
__device__ __nv_bfloat16 g_XsA[(size_t)2*QPIX*CH];      // cs[c]
__device__ __nv_bfloat16 g_XsB[(size_t)2*QPIX*CH];      // rh[c] / h[c]
__device__ float g_h[NN][CHW];
__device__ float g_cs[NN][CHW];
__device__ float g_rh[NN][CHW];
__device__ float g_z[CHW];
__device__ float g_o[CHW];
__device__ int   g_parent[NN];
__device__ int   g_ccount[NN];

__device__ __forceinline__ size_t wboff(int hsel, int type, int s) {
    return ((size_t)((hsel*3 + type)*2 + s)) * 9 * 512 * 512;
}

// ---------------- PTX helpers (sm_100 BASE features only) ----------------
__device__ __forceinline__ uint32_t smaddr(const void* p) {
    uint32_t a;
    asm("{ .reg .u64 t; cvta.to.shared.u64 t, %1; cvt.u32.u64 %0, t; }" : "=r"(a) : "l"(p));
    return a;
}
__device__ __forceinline__ void cpasync16(uint32_t s, const void* g) {
    asm volatile("cp.async.cg.shared.global [%0], [%1], 16;" :: "r"(s), "l"(g));
}
__device__ __forceinline__ void cpcommit() {
    asm volatile("cp.async.commit_group;" ::: "memory");
}
__device__ __forceinline__ void ldsm4(uint32_t* r, uint32_t addr) {
    asm volatile("ldmatrix.sync.aligned.m8n8.x4.shared.b16 {%0,%1,%2,%3}, [%4];"
                 : "=r"(r[0]), "=r"(r[1]), "=r"(r[2]), "=r"(r[3]) : "r"(addr));
}
__device__ __forceinline__ void mma16816(float* d, const uint32_t* a, const uint32_t* b) {
    asm volatile(
        "mma.sync.aligned.m16n8k16.row.col.f32.bf16.bf16.f32 "
        "{%0,%1,%2,%3}, {%4,%5,%6,%7}, {%8,%9}, {%0,%1,%2,%3};"
        : "+f"(d[0]), "+f"(d[1]), "+f"(d[2]), "+f"(d[3])
        : "r"(a[0]), "r"(a[1]), "r"(a[2]), "r"(a[3]), "r"(b[0]), "r"(b[1]));
}

// ---------------- setup kernels ----------------
__global__ void k_tree(const int* __restrict__ adj) {
    int t = threadIdx.x;
    if (t < NN) {
        int cnt = 0;
        for (int c = 0; c < NN; c++) cnt += (adj[t*NN + c] != 0);
        g_ccount[t] = cnt;
        int par = -1;
        for (int p = 0; p < NN; p++) if (adj[p*NN + t] != 0) par = p;
        g_parent[t] = par;
    }
}

__global__ void k_beta(const float* __restrict__ mw, const float* __restrict__ lang) {
    int n = blockIdx.x, co = threadIdx.x;
    __shared__ float sl[CL];
    for (int i = threadIdx.x; i < CL; i += blockDim.x) sl[i] = lang[n*CL + i];
    __syncthreads();
    const float* wrow = mw + (size_t)co*CIN_M + CV;
    float acc = 0.f;
    for (int k = 0; k < CL; k++) acc += wrow[k] * sl[k];
    g_beta[n][co] = acc;
}

__global__ void k_transw(const float* __restrict__ wr, const float* __restrict__ wu,
                         const float* __restrict__ wo) {
    const float* w = (blockIdx.z == 0) ? wr : ((blockIdx.z == 1) ? wu : wo);
    __shared__ float tile[32][33];
    int X0 = blockIdx.x * 32;   // over ci*9+tap, ci<512
    int co0 = blockIdx.y * 32;
    int tx = threadIdx.x, ty = threadIdx.y;
    tile[ty][tx] = w[(size_t)(co0 + ty) * (1024*9) + X0 + tx];
    __syncthreads();
    int X = X0 + ty;
    int ci = X / 9, tap = X % 9;
    g_Wt1[blockIdx.z][((size_t)tap*CH + ci)*CH + co0 + tx] = tile[tx][ty];
}

__global__ void k_wsplit(const float* __restrict__ wr, const float* __restrict__ wu,
                         const float* __restrict__ wo) {
    int l = blockIdx.x * 256 + threadIdx.x;     // 3*512*1024 total
    int type = l / (512*1024);
    int rem = l % (512*1024);
    int co = rem / 1024, ci = rem % 1024;
    const float* w = (type == 0) ? wr : ((type == 1) ? wu : wo);
    int hsel = ci >> 9, cil = ci & 511;
    const float* src = w + (size_t)(co*1024 + ci)*9;
#pragma unroll
    for (int tap = 0; tap < 9; tap++) {
        float v = src[tap];
        __nv_bfloat16 hi = __float2bfloat16(v);
        __nv_bfloat16 lo = __float2bfloat16(v - __bfloat162float(hi));
        size_t o = ((size_t)tap*512 + co)*512 + cil;
        g_Wb[wboff(hsel, type, 0) + o] = hi;
        g_Wb[wboff(hsel, type, 1) + o] = lo;
    }
}

__global__ void __launch_bounds__(256) k_visgemm(const float* __restrict__ mw,
                                                 const float* __restrict__ mb,
                                                 const float* __restrict__ vis) {
    __shared__ float As[16][64];
    __shared__ float Bs[16][64];
    int p0 = blockIdx.x * 64, co0 = blockIdx.y * 64;
    int tid = threadIdx.x;
    int cg = tid / 16, pg = tid % 16;
    float acc[4][4];
#pragma unroll
    for (int i = 0; i < 4; i++)
#pragma unroll
        for (int j = 0; j < 4; j++) acc[i][j] = 0.f;
    for (int k0 = 0; k0 < CV; k0 += 16) {
        __syncthreads();
        for (int l = tid; l < 64*16; l += 256) {
            int k = l % 16, co = l / 16;
            As[k][co] = mw[(size_t)(co0 + co)*CIN_M + k0 + k];
        }
        for (int l = tid; l < 16*64; l += 256) {
            int p = l % 64, k = l / 64;
            Bs[k][p] = vis[(size_t)(k0 + k)*PIX + p0 + p];
        }
        __syncthreads();
#pragma unroll
        for (int k = 0; k < 16; k++) {
            float4 a = *(const float4*)&As[k][cg*4];
            float4 b = *(const float4*)&Bs[k][pg*4];
            float av[4] = {a.x, a.y, a.z, a.w};
            float bv[4] = {b.x, b.y, b.z, b.w};
#pragma unroll
            for (int i = 0; i < 4; i++)
#pragma unroll
                for (int j = 0; j < 4; j++) acc[i][j] += av[i]*bv[j];
        }
    }
    for (int i = 0; i < 4; i++)
        for (int j = 0; j < 4; j++) {
            int co = co0 + cg*4 + i, p = p0 + pg*4 + j;
            g_vis[(size_t)co*PIX + p] = acc[i][j] + mb[co];
        }
}

__global__ void k_tapv() {
    int b = blockIdx.x;
    int type = b / (NN*9);
    int r = b % (NN*9);
    int n = r / 9, tap = r % 9;
    __shared__ float sb[CH];
    sb[threadIdx.x] = g_beta[n][threadIdx.x];
    __syncthreads();
    int co = threadIdx.x;
    const float* w = g_Wt1[type] + (size_t)tap*CH*CH + co;
    float acc = 0.f;
    for (int ci = 0; ci < CH; ci++) acc += w[(size_t)ci*CH] * sb[ci];
    g_tv[type][n][tap][co] = acc;
}

__global__ void k_cls() {
    int type = blockIdx.x / NN, n = blockIdx.x % NN;
    int co = threadIdx.x;
    float tv[9];
#pragma unroll
    for (int t = 0; t < 9; t++) tv[t] = g_tv[type][n][t][co];
#pragma unroll
    for (int yc = 0; yc < 3; yc++)
#pragma unroll
        for (int xc = 0; xc < 3; xc++) {
            float s = 0.f;
#pragma unroll
            for (int dy = 0; dy < 3; dy++) {
                if (yc == 0 && dy == 0) continue;
                if (yc == 2 && dy == 2) continue;
#pragma unroll
                for (int dx = 0; dx < 3; dx++) {
                    if (xc == 0 && dx == 0) continue;
                    if (xc == 2 && dx == 2) continue;
                    s += tv[dy*3 + dx];
                }
            }
            g_cls[type][n][yc*3 + xc][co] = s;
        }
}

// ---------------- input prep: fp32 [ci][px] -> bf16 hi/lo [pad-px][ci] ----------------
__global__ void k_prep(const float* __restrict__ in, __nv_bfloat16* __restrict__ out) {
    __shared__ float tile[64][65];
    int y = blockIdx.x;
    int ci0 = blockIdx.y * 64;
    int tid = threadIdx.x;
    for (int l = tid; l < 4096; l += 256) {
        int i = l >> 6, j = l & 63;
        tile[i][j] = in[(size_t)(ci0 + i)*PIX + y*64 + j];
    }
    __syncthreads();
    for (int l = tid; l < 4096; l += 256) {
        int j = l >> 6, i = l & 63;
        float v = tile[i][j];
        __nv_bfloat16 hi = __float2bfloat16(v);
        __nv_bfloat16 lo = __float2bfloat16(v - __bfloat162float(hi));
        size_t q = (size_t)(y + 1)*QDIM + (j + 1);
        out[q*CH + ci0 + i] = hi;
        out[(size_t)QPIX*CH + q*CH + ci0 + i] = lo;
    }
}

// ---------------- mma.sync conv core ----------------
// D[128co x 128px] = sum over 9 taps, 512 ci of (AhBh + AhBl + AlBh).
// 8 warps: warp w -> co block (w&3)*32, px block (w>>2)*64.
// Tiles per stage: [Ah | Al | Bh | Bl], each 128 rows x 128B (64 bf16), XOR-swizzled.
__device__ __forceinline__ void conv_mma(
    uint32_t sbase,
    const __nv_bfloat16* __restrict__ wbh, const __nv_bfloat16* __restrict__ wbl,
    const __nv_bfloat16* __restrict__ xs, int y0, int co0,
    float acc[2][8][4], bool doit)
{
    int tid = threadIdx.x;
    int l = tid & 31, w = tid >> 5;
    int wco = w & 3, wpx = w >> 2;
    if (!doit) return;

    const char* w0 = (const char*)(wbh + ((size_t)co0)*512);
    const char* w1 = (const char*)(wbl + ((size_t)co0)*512);
    const char* x0 = (const char*)xs;

    auto fill = [&](int s) {
        int tap = s >> 3, k0b = (s & 7) << 7;    // k0 bytes (64 ci * 2B)
        int dy = tap / 3, dx = tap % 3;
        uint32_t dst = sbase + (uint32_t)(s & 1)*STAGEB;
        size_t wtap = (size_t)tap*512*1024;      // bytes per tap block of [512co][512ci]
#pragma unroll
        for (int i = 0; i < 16; i++) {
            int chunk = tid + (i << 8);
            int t = chunk >> 10, r = (chunk >> 3) & 127, c = chunk & 7;
            uint32_t so = dst + (uint32_t)(t << 14) + (uint32_t)(r << 7)
                        + (uint32_t)(((c ^ (r & 7)) << 4));
            const char* src;
            if (t == 0)      src = w0 + wtap + (size_t)r*1024 + k0b + (c << 4);
            else if (t == 1) src = w1 + wtap + (size_t)r*1024 + k0b + (c << 4);
            else {
                int q = (y0 + (r >> 6) + dy)*QDIM + (r & 63) + dx;
                src = x0 + ((size_t)(t - 2)*QPIX + q)*1024 + k0b + (c << 4);
            }
            cpasync16(so, src);
        }
        cpcommit();
    };

    fill(0);
    for (int s = 0; s < NCHUNK; s++) {
        if (s + 1 < NCHUNK) {
            fill(s + 1);
            asm volatile("cp.async.wait_group 1;" ::: "memory");
        } else {
            asm volatile("cp.async.wait_group 0;" ::: "memory");
        }
        __syncthreads();
        uint32_t buf = sbase + (uint32_t)(s & 1)*STAGEB;
#pragma unroll
        for (int k = 0; k < 4; k++) {
            uint32_t ah[2][4], al[2][4];
#pragma unroll
            for (int mi = 0; mi < 2; mi++) {
                int row = wco*32 + mi*16 + (l & 15);
                int c = k*2 + ((l >> 4) & 1);
                uint32_t off = (uint32_t)((row << 7) + ((c ^ (row & 7)) << 4));
                ldsm4(ah[mi], buf + off);
                ldsm4(al[mi], buf + 16384 + off);
            }
            uint32_t bh[8][2], bl[8][2];
#pragma unroll
            for (int jj = 0; jj < 4; jj++) {
                int row = wpx*64 + jj*16 + ((l >> 4) & 1)*8 + (l & 7);
                int c = k*2 + ((l >> 3) & 1);
                uint32_t off = (uint32_t)((row << 7) + ((c ^ (row & 7)) << 4));
                uint32_t rh4[4], rl4[4];
                ldsm4(rh4, buf + 32768 + off);
                ldsm4(rl4, buf + 49152 + off);
                bh[2*jj][0] = rh4[0]; bh[2*jj][1] = rh4[1];
                bh[2*jj+1][0] = rh4[2]; bh[2*jj+1][1] = rh4[3];
                bl[2*jj][0] = rl4[0]; bl[2*jj][1] = rl4[1];
                bl[2*jj+1][0] = rl4[2]; bl[2*jj+1][1] = rl4[3];
            }
#pragma unroll
            for (int mi = 0; mi < 2; mi++)
#pragma unroll
                for (int nj = 0; nj < 8; nj++) {
                    mma16816(acc[mi][nj], ah[mi], bh[nj]);
                    mma16816(acc[mi][nj], ah[mi], bl[nj]);
                    mma16816(acc[mi][nj], al[mi], bh[nj]);
                }
        }
        __syncthreads();
    }
}

// ---------------- tk_pre: A[type] = conv(vis_part, W_half0[type]) + bias ----------------
__global__ void __launch_bounds__(256) tk_pre(const float* __restrict__ br,
                                              const float* __restrict__ bu,
                                              const float* __restrict__ bo) {
    extern __shared__ char dsm[];
    uint32_t sbase = (smaddr(dsm) + 127u) & ~127u;
    int y0 = blockIdx.x * 2, co0 = blockIdx.y * 128;
    int type = blockIdx.z;
    const float* bias = (type == 0) ? br : ((type == 1) ? bu : bo);

    float acc[2][8][4];
#pragma unroll
    for (int a = 0; a < 2; a++)
#pragma unroll
        for (int b = 0; b < 8; b++)
#pragma unroll
            for (int e = 0; e < 4; e++) acc[a][b][e] = 0.f;

    conv_mma(sbase, g_Wb + wboff(0, type, 0), g_Wb + wboff(0, type, 1),
             g_XsP, y0, co0, acc, true);

    int l = threadIdx.x & 31, w = threadIdx.x >> 5;
    int co_w = co0 + (w & 3)*32;
    int px_w = blockIdx.x*128 + (w >> 2)*64;
    float* out = &g_A[type][0];
#pragma unroll
    for (int mi = 0; mi < 2; mi++)
#pragma unroll
        for (int nj = 0; nj < 8; nj++)
#pragma unroll
            for (int e = 0; e < 4; e++) {
                int co = co_w + mi*16 + (l >> 2) + ((e >> 1) << 3);
                int px = px_w + nj*8 + ((l & 3) << 1) + (e & 1);
                out[(size_t)co*PIX + px] = acc[mi][nj][e] + bias[co];
            }
}

// ---------------- tk_zo: z.z==0 -> z = sigmoid(conv(cs)+A_u+cls_u); ==1 -> o = tanh(conv(rh)+A_o+cls_o)
__global__ void __launch_bounds__(256) tk_zo(int node) {
    extern __shared__ char dsm[];
    uint32_t sbase = (smaddr(dsm) + 127u) & ~127u;
    int y0 = blockIdx.x * 2, co0 = blockIdx.y * 128;
    int which = blockIdx.z;
    int type = which ? T_OUT : T_UPD;
    bool leaf = (g_ccount[node] == 0);

    float acc[2][8][4];
#pragma unroll
    for (int a = 0; a < 2; a++)
#pragma unroll
        for (int b = 0; b < 8; b++)
#pragma unroll
            for (int e = 0; e < 4; e++) acc[a][b][e] = 0.f;

    conv_mma(sbase, g_Wb + wboff(1, type, 0), g_Wb + wboff(1, type, 1),
             which ? g_XsB : g_XsA, y0, co0, acc, !leaf);

    int l = threadIdx.x & 31, w = threadIdx.x >> 5;
    int co_w = co0 + (w & 3)*32;
    int px_w = blockIdx.x*128 + (w >> 2)*64;
    const float* base = &g_A[type][0];
    const float* cls = &g_cls[type][node][0][0];
    float* out = which ? g_o : g_z;
#pragma unroll
    for (int mi = 0; mi < 2; mi++)
#pragma unroll
        for (int nj = 0; nj < 8; nj++)
#pragma unroll
            for (int e = 0; e < 4; e++) {
                int co = co_w + mi*16 + (l >> 2) + ((e >> 1) << 3);
                int px = px_w + nj*8 + ((l & 3) << 1) + (e & 1);
                int row = px >> 6, col = px & 63;
                int yc = (row == 0) ? 0 : ((row == HH - 1) ? 2 : 1);
                int xc = (col == 0) ? 0 : ((col == WW - 1) ? 2 : 1);
                size_t idx = (size_t)co*PIX + px;
                float v = acc[mi][nj][e] + base[idx] + cls[(yc*3 + xc)*CH + co];
                out[idx] = which ? tanhf(v) : (1.f / (1.f + __expf(-v)));
            }
}

// ---------------- tk_rst: r = sigmoid(conv(h[c])+A_r+cls_r[par]); rh[par]+=r*h; cs[par]+=h
__global__ void __launch_bounds__(256) tk_rst(int child) {
    extern __shared__ char dsm[];
    uint32_t sbase = (smaddr(dsm) + 127u) & ~127u;
    int y0 = blockIdx.x * 2, co0 = blockIdx.y * 128;

    float acc[2][8][4];
#pragma unroll
    for (int a = 0; a < 2; a++)
#pragma unroll
        for (int b = 0; b < 8; b++)
#pragma unroll
            for (int e = 0; e < 4; e++) acc[a][b][e] = 0.f;

    conv_mma(sbase, g_Wb + wboff(1, T_RST, 0), g_Wb + wboff(1, T_RST, 1),
             g_XsB, y0, co0, acc, true);

    int l = threadIdx.x & 31, w = threadIdx.x >> 5;
    int co_w = co0 + (w & 3)*32;
    int px_w = blockIdx.x*128 + (w >> 2)*64;
    int par = g_parent[child];
    const float* base = &g_A[T_RST][0];
    const float* cls = &g_cls[T_RST][par][0][0];
    const float* hin = &g_h[child][0];
    float* rh = &g_rh[par][0];
    float* cs = &g_cs[par][0];
#pragma unroll
    for (int mi = 0; mi < 2; mi++)
#pragma unroll
        for (int nj = 0; nj < 8; nj++)
#pragma unroll
            for (int e = 0; e < 4; e++) {
                int co = co_w + mi*16 + (l >> 2) + ((e >> 1) << 3);
                int px = px_w + nj*8 + ((l & 3) << 1) + (e & 1);
                int row = px >> 6, col = px & 63;
                int yc = (row == 0) ? 0 : ((row == HH - 1) ? 2 : 1);
                int xc = (col == 0) ? 0 : ((col == WW - 1) ? 2 : 1);
                size_t idx = (size_t)co*PIX + px;
                float v = acc[mi][nj][e] + base[idx] + cls[(yc*3 + xc)*CH + co];
                float rg = 1.f / (1.f + __expf(-v));
                float hv = hin[idx];
                rh[idx] += rg * hv;
                cs[idx] += hv;
            }
}

// ---------------- h = (1-z)*o + z*ch_sum ----------------
__global__ void k_h(const float* __restrict__ cs, float* __restrict__ h) {
    int i = blockIdx.x * blockDim.x + threadIdx.x;
    float z = g_z[i], o = g_o[i];
    h[i] = (1.f - z)*o + z*cs[i];
}

// ---------------- host orchestration ----------------
extern "C" void kernel_launch(void* const* d_in, const int* in_sizes, int n_in,
                              void* d_out, int out_size) {
    const float* vis  = (const float*)d_in[0];
    const float* lang = (const float*)d_in[1];
    const int*   adj  = (const int*)  d_in[2];
    const float* mw   = (const float*)d_in[3];
    const float* mb   = (const float*)d_in[4];
    const float* wr   = (const float*)d_in[5];
    const float* br   = (const float*)d_in[6];
    const float* wu   = (const float*)d_in[7];
    const float* bu   = (const float*)d_in[8];
    const float* wo   = (const float*)d_in[9];
    const float* bo   = (const float*)d_in[10];

    float *p_vis, *p_h, *p_cs, *p_rh;
    __nv_bfloat16 *p_XsP, *p_XsA, *p_XsB;
    cudaGetSymbolAddress((void**)&p_vis, g_vis);
    cudaGetSymbolAddress((void**)&p_h,   g_h);
    cudaGetSymbolAddress((void**)&p_cs,  g_cs);
    cudaGetSymbolAddress((void**)&p_rh,  g_rh);
    cudaGetSymbolAddress((void**)&p_XsP, g_XsP);
    cudaGetSymbolAddress((void**)&p_XsA, g_XsA);
    cudaGetSymbolAddress((void**)&p_XsB, g_XsB);

    cudaFuncSetAttribute(tk_pre, cudaFuncAttributeMaxDynamicSharedMemorySize, DSMEM);
    cudaFuncSetAttribute(tk_zo,  cudaFuncAttributeMaxDynamicSharedMemorySize, DSMEM);
    cudaFuncSetAttribute(tk_rst, cudaFuncAttributeMaxDynamicSharedMemorySize, DSMEM);

    size_t xsbytes = sizeof(__nv_bfloat16)*(size_t)2*QPIX*CH;
    cudaMemsetAsync(p_XsP, 0, xsbytes);
    cudaMemsetAsync(p_XsA, 0, xsbytes);
    cudaMemsetAsync(p_XsB, 0, xsbytes);

    k_tree<<<1, 32>>>(adj);
    k_beta<<<NN, CH>>>(mw, lang);
    k_transw<<<dim3(4608/32, CH/32, 3), dim3(32, 32)>>>(wr, wu, wo);
    k_wsplit<<<(3*512*1024)/256, 256>>>(wr, wu, wo);
    k_visgemm<<<dim3(PIX/64, CH/64), 256>>>(mw, mb, vis);
    k_prep<<<dim3(64, 8), 256>>>(p_vis, p_XsP);

    tk_pre<<<dim3(32, 4, 3), 256, DSMEM>>>(br, bu, bo);

    k_tapv<<<3*NN*9, CH>>>();
    k_cls<<<3*NN, CH>>>();

    cudaMemsetAsync(p_cs, 0, sizeof(float)*(size_t)NN*CHW);
    cudaMemsetAsync(p_rh, 0, sizeof(float)*(size_t)NN*CHW);

    for (int c = NN - 1; c >= 0; c--) {
        k_prep<<<dim3(64, 8), 256>>>(p_cs + (size_t)c*CHW, p_XsA);
        k_prep<<<dim3(64, 8), 256>>>(p_rh + (size_t)c*CHW, p_XsB);
        tk_zo<<<dim3(32, 4, 2), 256, DSMEM>>>(c);
        k_h<<<CHW/256, 256>>>(p_cs + (size_t)c*CHW, p_h + (size_t)c*CHW);
        if (c > 0) {
            k_prep<<<dim3(64, 8), 256>>>(p_h + (size_t)c*CHW, p_XsB);
            tk_rst<<<dim3(32, 4), 256, DSMEM>>>(c);
        }
    }

    cudaMemcpyAsync(d_out, p_h, sizeof(float)*(size_t)CHW, cudaMemcpyDeviceToDevice);
}